// round 4
// baseline (speedup 1.0000x reference)
#include <cuda_runtime.h>
#include <cstdint>

// ---------------------------------------------------------------------------
// Gcs_loss, expanded form:
//   v = pred - truth, halves X = v[:,:P], Y = v[:,P:]
//   s_i = S2 - 2 * sum_b v[b,i]*rowsum[b] + P * sum_b v[b,i]^2
//   out = ( sum_i sqrt(s_i^X) + sum_i sqrt(s_i^Y) ) / (2B)
// B=32, P=1024.
//
// Grid = 16 CTAs = 2 clusters of 8 (cluster == one half, rank == column slice).
// ONE cluster.sync (overlapped with global loads); all other cross-CTA
// communication is push-style st.async + mbarrier (no remote reads, no
// trailing barrier). Cross-half combine via release-atomic + acquire loads.
// ---------------------------------------------------------------------------

#define GB      32
#define GP      1024
#define SCOLS   128            // columns per slice (8 slices per half)

__device__ float        g_bs[2];   // per-half sum of sqrts (plain stores, idempotent)
__device__ unsigned int g_done;    // cross-half completion counter (reset each launch)

// ---------------- tiny PTX helpers ----------------
__device__ __forceinline__ uint32_t smem_u32(const void* p) {
    uint32_t a;
    asm("{ .reg .u64 t; cvta.to.shared.u64 t, %1; cvt.u32.u64 %0, t; }"
        : "=r"(a) : "l"(p));
    return a;
}
__device__ __forceinline__ uint32_t mapa_rank(uint32_t smem_addr, uint32_t rank) {
    uint32_t r;
    asm("mapa.shared::cluster.u32 %0, %1, %2;" : "=r"(r) : "r"(smem_addr), "r"(rank));
    return r;
}
__device__ __forceinline__ void mbar_init(uint32_t mbar, uint32_t count) {
    asm volatile("mbarrier.init.shared.b64 [%0], %1;" :: "r"(mbar), "r"(count) : "memory");
}
__device__ __forceinline__ void mbar_expect_tx(uint32_t mbar, uint32_t bytes) {
    asm volatile("mbarrier.arrive.expect_tx.shared.b64 _, [%0], %1;"
                 :: "r"(mbar), "r"(bytes) : "memory");
}
__device__ __forceinline__ void mbar_wait(uint32_t mbar, uint32_t parity) {
    uint32_t done;
    asm volatile(
        "{\n\t.reg .pred p;\n\t"
        "mbarrier.try_wait.parity.acquire.cta.shared::cta.b64 p, [%1], %2;\n\t"
        "selp.b32 %0, 1, 0, p;\n\t}"
        : "=r"(done) : "r"(mbar), "r"(parity) : "memory");
    if (!done) {
        asm volatile(
            "{\n\t.reg .pred P1;\n\t"
            "WL_%=:\n\t"
            "mbarrier.try_wait.parity.acquire.cta.shared::cta.b64 P1, [%0], %1, 0x989680;\n\t"
            "@P1 bra.uni WD_%=;\n\t"
            "bra.uni WL_%=;\n\t"
            "WD_%=:\n\t}"
            :: "r"(mbar), "r"(parity) : "memory");
    }
}
__device__ __forceinline__ void st_async_b64(uint32_t dst, float a, float b, uint32_t mbar) {
    float2 v = make_float2(a, b);
    unsigned long long bits = *reinterpret_cast<unsigned long long*>(&v);
    asm volatile("st.async.shared::cluster.mbarrier::complete_tx::bytes.b64 [%0], %1, [%2];"
                 :: "r"(dst), "l"(bits), "r"(mbar) : "memory");
}
__device__ __forceinline__ void st_async_b32(uint32_t dst, float a, uint32_t mbar) {
    asm volatile("st.async.shared::cluster.mbarrier::complete_tx::bytes.b32 [%0], %1, [%2];"
                 :: "r"(dst), "r"(__float_as_uint(a)), "r"(mbar) : "memory");
}
__device__ __forceinline__ unsigned atom_add_release_gpu(unsigned int* p, unsigned v) {
    unsigned old;
    asm volatile("atom.release.gpu.global.add.u32 %0, [%1], %2;"
                 : "=r"(old) : "l"(p), "r"(v) : "memory");
    return old;
}
__device__ __forceinline__ float ld_acquire_gpu_f32(const float* p) {
    float v;
    asm volatile("ld.acquire.gpu.global.f32 %0, [%1];" : "=f"(v) : "l"(p) : "memory");
    return v;
}

// ---------------------------------------------------------------------------

__global__ void __launch_bounds__(1024, 1) __cluster_dims__(8, 1, 1)
gcs_loss_kernel(const float* __restrict__ pred,
                const float* __restrict__ truth,
                float* __restrict__ out)
{
    __shared__ float  sv[GB * SCOLS];         // 16 KB: v slice [32 rows][128 cols]
    __shared__ float2 s_parts[8][GB];         // [src_rank][row] = (rowsum, sq) pushed by peers
    __shared__ float  s_bsums[8];             // rank0 only: per-rank block sums
    __shared__ float  s_rowsum[GB];
    __shared__ float  s_S2;
    __shared__ float  s_red[4];
    __shared__ __align__(8) unsigned long long mbar1;   // partials exchange
    __shared__ __align__(8) unsigned long long mbar2;   // tail (rank0)

    const int bid   = blockIdx.x;
    const int half  = bid >> 3;        // 0 = X, 1 = Y  (cluster id)
    const int slice = bid & 7;         // rank within cluster
    const int tid   = threadIdx.x;     // 0..1023
    const int row   = tid >> 5;        // warp w == row w
    const int lane  = tid & 31;

    const uint32_t mbar1_a = smem_u32(&mbar1);
    const uint32_t mbar2_a = smem_u32(&mbar2);

    // ---- issue global loads FIRST (latency hides behind init + cluster.sync)
    const float* pb = pred  + row * (2 * GP) + half * GP + slice * SCOLS;
    const float* tb = truth + row * (2 * GP) + half * GP + slice * SCOLS;
    float4 p = ((const float4*)pb)[lane];
    float4 t = ((const float4*)tb)[lane];

    // ---- mbarrier init + expect while loads are in flight ----
    if (tid == 0) {
        mbar_init(mbar1_a, 1);
        mbar_expect_tx(mbar1_a, 8 * GB * 8);          // 8 ranks x 32 rows x 8 B = 2048
        if (slice == 0) {
            mbar_init(mbar2_a, 1);
            mbar_expect_tx(mbar2_a, 8 * 4);           // 8 ranks x 4 B
        }
    }

    // single cluster barrier: mbarriers visible cluster-wide before any st.async
    asm volatile("barrier.cluster.arrive.aligned;" ::: "memory");
    asm volatile("barrier.cluster.wait.aligned;"   ::: "memory");

    // ---- Phase 1: v = p - t, store slice, per-row rowsum & sumsq ----------
    float4 v;
    v.x = p.x - t.x; v.y = p.y - t.y; v.z = p.z - t.z; v.w = p.w - t.w;
    ((float4*)(sv + row * SCOLS))[lane] = v;

    float rs = (v.x + v.y) + (v.z + v.w);
    float sq = v.x * v.x + v.y * v.y + v.z * v.z + v.w * v.w;
    #pragma unroll
    for (int off = 16; off; off >>= 1) {
        rs += __shfl_xor_sync(0xffffffff, rs, off);
        sq += __shfl_xor_sync(0xffffffff, sq, off);
    }

    // lane0 of each warp pushes (rs, sq) for its row to ALL 8 ranks, ASAP
    if (lane == 0) {
        uint32_t slot = smem_u32(&s_parts[slice][row]);
        #pragma unroll
        for (int r = 0; r < 8; r++)
            st_async_b64(mapa_rank(slot, r), rs, sq, mapa_rank(mbar1_a, r));
    }
    __syncthreads();     // sv fully written (needed by phase 2)

    // ---- warp 0: wait for all partials, build rowsums + S2 ----------------
    if (tid < 32) {
        mbar_wait(mbar1_a, 0);
        float rtot = 0.f, sqrow = 0.f;
        #pragma unroll
        for (int s = 0; s < 8; s++) {
            float2 m = s_parts[s][lane];
            rtot  += m.x;
            sqrow += m.y;
        }
        s_rowsum[lane] = rtot;
        #pragma unroll
        for (int off = 16; off; off >>= 1)
            sqrow += __shfl_xor_sync(0xffffffff, sqrow, off);
        if (lane == 0) s_S2 = sqrow;
    }
    __syncthreads();

    // ---- Phase 2: per-anchor distance (128 anchors/block) -----------------
    if (tid < SCOLS) {
        float dot = 0.f, colsq = 0.f;
        #pragma unroll
        for (int b = 0; b < GB; b++) {
            float vv = sv[b * SCOLS + tid];
            dot   += vv * s_rowsum[b];
            colsq += vv * vv;
        }
        float s   = s_S2 - 2.0f * dot + (float)GP * colsq;
        float val = sqrtf(fmaxf(s, 0.0f));
        #pragma unroll
        for (int off = 16; off; off >>= 1)
            val += __shfl_xor_sync(0xffffffff, val, off);
        if (lane == 0) s_red[tid >> 5] = val;
    }
    __syncthreads();

    // ---- tail: push block sum to rank0, rank0 combines ---------------------
    if (tid == 0) {
        float bs = s_red[0] + s_red[1] + s_red[2] + s_red[3];
        uint32_t dst = smem_u32(&s_bsums[slice]);
        st_async_b32(mapa_rank(dst, 0), bs, mapa_rank(mbar2_a, 0));

        if (slice == 0) {
            mbar_wait(mbar2_a, 0);
            float hs = 0.f;
            #pragma unroll
            for (int s = 0; s < 8; s++) hs += s_bsums[s];
            g_bs[half] = hs;                       // plain store, idempotent
            unsigned prev = atom_add_release_gpu(&g_done, 1u);
            if (prev == 1) {                       // last half: final combine
                float a = ld_acquire_gpu_f32(&g_bs[0]);
                float c = ld_acquire_gpu_f32(&g_bs[1]);
                *out = (a + c) * (1.0f / (float)(GB * 2));
                g_done = 0;                        // reset for next replay
            }
        }
    }
    // no trailing cluster barrier: all cross-CTA traffic is push-style and
    // acknowledged by rank0's mbarrier wait before rank0 exits.
}

extern "C" void kernel_launch(void* const* d_in, const int* in_sizes, int n_in,
                              void* d_out, int out_size)
{
    (void)in_sizes; (void)n_in; (void)out_size;
    const float* pred  = (const float*)d_in[0];
    const float* truth = (const float*)d_in[1];
    float* out = (float*)d_out;

    gcs_loss_kernel<<<16, 1024>>>(pred, truth, out);
}